// round 16
// baseline (speedup 1.0000x reference)
#include <cuda_runtime.h>
#include <cuda_fp16.h>
#include <math.h>
#include <cstdint>

#define NN 100000
#define NE 625000
#define HH 128
#define H2 256
#define GG 64
#define NHOPS 5
#define EPSV 1e-5f

// ---------------- scratch (static device globals; no allocation) ----------------
static __device__ float  g_h  [(size_t)NN * HH];
static __device__ float  g_deg [NN];
static __device__ float  g_dinv[NN];
static __device__ float  g_vn  [GG * HH];
static __device__ float  g_vnh [GG * H2];
static __device__ float  g_pool[GG * HH];
static __device__ float  g_cnt [GG];
static __device__ double g_sum  [HH];
static __device__ double g_sumsq[HH];
static __device__ float  g_bnA[HH];
static __device__ float  g_bnC[HH];
// CSR
static __device__ int g_icnt[NN];
static __device__ int g_scan[NN];
static __device__ int g_bsum[512];
static __device__ int g_rowptr[NN + 1];
static __device__ int g_fill[NN];
static __device__ int g_ecol[NE];
// fp16 hi/lo split buffers: x lives ONLY as (ahi+alo); hidden as (hhi+hlo)
static __device__ __half g_ahi[(size_t)NN * HH];
static __device__ __half g_alo[(size_t)NN * HH];
static __device__ __half g_hhi[(size_t)NN * H2];
static __device__ __half g_hlo[(size_t)NN * H2];
// transposed + split weights: [N,K] row-major fp16 hi/lo
#define WTOT 475136
static __device__ __half g_whi[WTOT];
static __device__ __half g_wlo[WTOT];
#define OW_PRE1 0
#define OW_PRE2 32768
#define OW_CONV(i) (65536 + (i) * 16384)
#define OW_FFN1(i) (147456 + (i) * 32768)
#define OW_FFN2(i) (311296 + (i) * 32768)

__device__ __forceinline__ float gelu_f(float x) {
    return 0.5f * x * (1.0f + erff(x * 0.70710678118654752f));
}
__device__ __forceinline__ uint32_t smem_u32(const void* p) {
    uint32_t a;
    asm("{ .reg .u64 t; cvta.to.shared.u64 t, %1; cvt.u32.u64 %0, t; }" : "=r"(a) : "l"(p));
    return a;
}
__device__ __forceinline__ void ldsm4(uint32_t& r0, uint32_t& r1, uint32_t& r2, uint32_t& r3,
                                      uint32_t addr) {
    asm volatile("ldmatrix.sync.aligned.m8n8.x4.shared.b16 {%0,%1,%2,%3}, [%4];"
                 : "=r"(r0), "=r"(r1), "=r"(r2), "=r"(r3) : "r"(addr));
}
__device__ __forceinline__ void mma_f16(float* c, uint32_t a0, uint32_t a1, uint32_t a2,
                                        uint32_t a3, uint32_t b0, uint32_t b1) {
    asm volatile("mma.sync.aligned.m16n8k16.row.col.f32.f16.f16.f32 "
                 "{%0,%1,%2,%3}, {%4,%5,%6,%7}, {%8,%9}, {%0,%1,%2,%3};"
                 : "+f"(c[0]), "+f"(c[1]), "+f"(c[2]), "+f"(c[3])
                 : "r"(a0), "r"(a1), "r"(a2), "r"(a3), "r"(b0), "r"(b1));
}
__device__ __forceinline__ void cp16(uint32_t dst, const void* src, int sz) {
    asm volatile("cp.async.cg.shared.global [%0], [%1], 16, %2;"
                 :: "r"(dst), "l"(src), "r"(sz) : "memory");
}
// L1-cached variant for weight (B) tiles: re-read by every M-CTA -> keep in L1
__device__ __forceinline__ void cp16ca(uint32_t dst, const void* src) {
    asm volatile("cp.async.ca.shared.global [%0], [%1], 16;"
                 :: "r"(dst), "l"(src) : "memory");
}
#define CP_COMMIT() asm volatile("cp.async.commit_group;" ::: "memory")
#define CP_WAIT(n)  asm volatile("cp.async.wait_group %0;" :: "n"(n) : "memory")

// ==== 3-term fp16 GEMM: CTA 128x64, warp 32x32, 3 CTAs/SM ====
// C = epi(A@Wt^T), terms ah*bh + al*bh + ah*bl (drop ~2^-22).
// FLAGS: 1=+bias 2=gelu 4=+Res(from split) 8=write hi/lo split 16=write fp32 C
#define KC 32
#define ROWB 80
#define ABUF (128 * ROWB)            // 10240
#define BBUF (64 * ROWB)             // 5120
#define STGB (2 * ABUF + 2 * BBUF)   // 30720 per stage
#define GSMEM (2 * STGB)             // 61440

template <int FLAGS>
__global__ void __launch_bounds__(256, 3) mma_gemm(
    const __half* __restrict__ Ahi, const __half* __restrict__ Alo,
    const __half* __restrict__ Bhi, const __half* __restrict__ Blo,
    const float* __restrict__ bias,
    const __half* __restrict__ Reshi, const __half* __restrict__ Reslo,
    float* __restrict__ C, __half* __restrict__ Chi, __half* __restrict__ Clo,
    int M, int K, int Nc)
{
    extern __shared__ char sm[];
    uint32_t sb = smem_u32(sm);

    int t = threadIdx.x;
    int lid = t & 31, wid = t >> 5;
    int wm = wid & 3, wn = wid >> 2;
    int m0 = blockIdx.y * 128, n0 = blockIdx.x * 64;
    int nchunks = K / KC;

    float acc[2][4][4];
    #pragma unroll
    for (int i = 0; i < 2; i++)
        #pragma unroll
        for (int j = 0; j < 4; j++)
            #pragma unroll
            for (int k = 0; k < 4; k++) acc[i][j][k] = 0.f;

    auto issue = [&](int ch) {
        uint32_t st = sb + (uint32_t)(ch & 1) * STGB;
        int k0 = ch * KC;
        #pragma unroll
        for (int i = 0; i < 2; i++) {
            int c = t + i * 256;
            int r = c >> 2;
            int kcEl = (c & 3) * 8;
            uint32_t doff = (uint32_t)r * ROWB + (uint32_t)kcEl * 2;
            int ar = m0 + r;
            int okA = (ar < M) ? 16 : 0;
            int arc = okA ? ar : 0;
            cp16(st + doff,        Ahi + (size_t)arc * K + k0 + kcEl, okA);
            cp16(st + ABUF + doff, Alo + (size_t)arc * K + k0 + kcEl, okA);
        }
        {
            int c = t;
            int r = c >> 2;
            int kcEl = (c & 3) * 8;
            uint32_t doff = (uint32_t)r * ROWB + (uint32_t)kcEl * 2;
            int br = n0 + r;
            cp16ca(st + 2 * ABUF + doff,        Bhi + (size_t)br * K + k0 + kcEl);
            cp16ca(st + 2 * ABUF + BBUF + doff, Blo + (size_t)br * K + k0 + kcEl);
        }
        CP_COMMIT();
    };

    issue(0);
    for (int ch = 0; ch < nchunks; ch++) {
        if (ch + 1 < nchunks) { issue(ch + 1); CP_WAIT(1); }
        else                  { CP_WAIT(0); }
        __syncthreads();

        uint32_t st  = sb + (uint32_t)(ch & 1) * STGB;
        uint32_t sAh = st, sAl = st + ABUF;
        uint32_t sBh = st + 2 * ABUF, sBl = st + 2 * ABUF + BBUF;

        #pragma unroll
        for (int ks = 0; ks < 2; ks++) {
            int kk = ks * 16;
            uint32_t ah[2][4], al[2][4];
            #pragma unroll
            for (int mr = 0; mr < 2; mr++) {
                int row = wm * 32 + mr * 16 + (lid & 15);
                uint32_t off = (uint32_t)row * ROWB + ((uint32_t)kk + (lid >> 4) * 8) * 2;
                ldsm4(ah[mr][0], ah[mr][1], ah[mr][2], ah[mr][3], sAh + off);
                ldsm4(al[mr][0], al[mr][1], al[mr][2], al[mr][3], sAl + off);
            }
            uint32_t bh[2][4], bl[2][4];
            #pragma unroll
            for (int np = 0; np < 2; np++) {
                int brow = wn * 32 + np * 16 + (lid & 7) + ((lid >> 4) & 1) * 8;
                uint32_t off = (uint32_t)brow * ROWB + ((uint32_t)kk + ((lid >> 3) & 1) * 8) * 2;
                ldsm4(bh[np][0], bh[np][1], bh[np][2], bh[np][3], sBh + off);
                ldsm4(bl[np][0], bl[np][1], bl[np][2], bl[np][3], sBl + off);
            }
            #pragma unroll
            for (int np = 0; np < 2; np++)
                #pragma unroll
                for (int mr = 0; mr < 2; mr++) {
                    mma_f16(acc[mr][np * 2],     ah[mr][0], ah[mr][1], ah[mr][2], ah[mr][3],
                            bh[np][0], bh[np][1]);
                    mma_f16(acc[mr][np * 2 + 1], ah[mr][0], ah[mr][1], ah[mr][2], ah[mr][3],
                            bh[np][2], bh[np][3]);
                }
            #pragma unroll
            for (int np = 0; np < 2; np++)
                #pragma unroll
                for (int mr = 0; mr < 2; mr++) {
                    mma_f16(acc[mr][np * 2],     al[mr][0], al[mr][1], al[mr][2], al[mr][3],
                            bh[np][0], bh[np][1]);
                    mma_f16(acc[mr][np * 2 + 1], al[mr][0], al[mr][1], al[mr][2], al[mr][3],
                            bh[np][2], bh[np][3]);
                }
            #pragma unroll
            for (int np = 0; np < 2; np++)
                #pragma unroll
                for (int mr = 0; mr < 2; mr++) {
                    mma_f16(acc[mr][np * 2],     ah[mr][0], ah[mr][1], ah[mr][2], ah[mr][3],
                            bl[np][0], bl[np][1]);
                    mma_f16(acc[mr][np * 2 + 1], ah[mr][0], ah[mr][1], ah[mr][2], ah[mr][3],
                            bl[np][2], bl[np][3]);
                }
        }
        __syncthreads();
    }

    // vectorized epilogue: (col,col+1) pairs
    #pragma unroll
    for (int mr = 0; mr < 2; mr++) {
        #pragma unroll
        for (int nc = 0; nc < 4; nc++) {
            int col = n0 + wn * 32 + nc * 8 + (lid & 3) * 2;
            #pragma unroll
            for (int hf = 0; hf < 2; hf++) {
                int row = m0 + wm * 32 + mr * 16 + (lid >> 2) + hf * 8;
                if (row >= M) continue;
                float v0 = acc[mr][nc][hf * 2 + 0];
                float v1 = acc[mr][nc][hf * 2 + 1];
                if (FLAGS & 1) { v0 += bias[col]; v1 += bias[col + 1]; }
                if (FLAGS & 2) { v0 = gelu_f(v0); v1 = gelu_f(v1); }
                size_t gidx = (size_t)row * Nc + col;
                if (FLAGS & 4) {
                    __half2 rh = *reinterpret_cast<const __half2*>(Reshi + gidx);
                    __half2 rl = *reinterpret_cast<const __half2*>(Reslo + gidx);
                    v0 += __low2float(rh)  + __low2float(rl);
                    v1 += __high2float(rh) + __high2float(rl);
                }
                if (FLAGS & 16)
                    *reinterpret_cast<float2*>(C + gidx) = make_float2(v0, v1);
                if (FLAGS & 8) {
                    __half h0 = __float2half_rn(v0), h1 = __float2half_rn(v1);
                    *reinterpret_cast<__half2*>(Chi + gidx) = __halves2half2(h0, h1);
                    *reinterpret_cast<__half2*>(Clo + gidx) = __floats2half2_rn(
                        v0 - __half2float(h0), v1 - __half2float(h1));
                }
            }
        }
    }
}

// ======================= fused weight prep (fp16 hi/lo, transposed) =======================
__global__ void wprep_all_k(const float* __restrict__ pre_W1, const float* __restrict__ pre_W2,
                            const float* __restrict__ conv_W, const float* __restrict__ ffn_W1,
                            const float* __restrict__ ffn_W2) {
    int i = blockIdx.x * blockDim.x + threadIdx.x;
    if (i >= WTOT) return;
    const float* src; int K, Nc, off;
    if (i < 32768)       { src = pre_W1; K = HH; Nc = H2; off = i; }
    else if (i < 65536)  { src = pre_W2; K = H2; Nc = HH; off = i - 32768; }
    else if (i < 147456) { int l = (i - 65536) >> 14; src = conv_W + l * 16384;
                           K = HH; Nc = HH; off = (i - 65536) & 16383; }
    else if (i < 311296) { int l = (i - 147456) >> 15; src = ffn_W1 + (size_t)l * 32768;
                           K = HH; Nc = H2; off = (i - 147456) & 32767; }
    else                 { int l = (i - 311296) >> 15; src = ffn_W2 + (size_t)l * 32768;
                           K = H2; Nc = HH; off = (i - 311296) & 32767; }
    int n = off / K, k = off - n * K;
    float v = src[(size_t)k * Nc + n];
    __half h = __float2half_rn(v);
    g_whi[i] = h;
    g_wlo[i] = __float2half_rn(v - __half2float(h));
}
// split input x (4 elems/thread)
__global__ void split_k(const float* __restrict__ X, __half* __restrict__ hi,
                        __half* __restrict__ lo, int n4) {
    int i = blockIdx.x * blockDim.x + threadIdx.x;   // over n/4
    if (i >= n4) return;
    float4 v = reinterpret_cast<const float4*>(X)[i];
    __half h0 = __float2half_rn(v.x), h1 = __float2half_rn(v.y);
    __half h2 = __float2half_rn(v.z), h3 = __float2half_rn(v.w);
    reinterpret_cast<__half2*>(hi)[i * 2]     = __halves2half2(h0, h1);
    reinterpret_cast<__half2*>(hi)[i * 2 + 1] = __halves2half2(h2, h3);
    reinterpret_cast<__half2*>(lo)[i * 2]     = __floats2half2_rn(
        v.x - __half2float(h0), v.y - __half2float(h1));
    reinterpret_cast<__half2*>(lo)[i * 2 + 1] = __floats2half2_rn(
        v.z - __half2float(h2), v.w - __half2float(h3));
}

// ---------------- small SIMT GEMM (final post-FFNN, G=64 rows) ----------------
template <int FLAGS>
__global__ void gemm64(const float* __restrict__ A, const float* __restrict__ W,
                       const float* __restrict__ bias, const float* __restrict__ Res,
                       float* __restrict__ C, int M, int K, int Nc)
{
    const int BM = 64, BN = 64, BK = 16;
    __shared__ float As[BK][BM + 4];
    __shared__ float Ws[BK][BN];
    int t  = threadIdx.x;
    int tx = t & 15, ty = t >> 4;
    int m0 = blockIdx.y * BM, n0 = blockIdx.x * BN;
    float acc[4][4] = {};
    int la_m = t >> 2, la_k = (t & 3) * 4;
    int lw_k = t >> 4, lw_n = (t & 15) * 4;
    for (int k0 = 0; k0 < K; k0 += BK) {
        int arow = m0 + la_m;
        if (arow < M) {
            float4 v = *reinterpret_cast<const float4*>(A + (size_t)arow * K + k0 + la_k);
            As[la_k + 0][la_m] = v.x; As[la_k + 1][la_m] = v.y;
            As[la_k + 2][la_m] = v.z; As[la_k + 3][la_m] = v.w;
        } else {
            As[la_k + 0][la_m] = 0.f; As[la_k + 1][la_m] = 0.f;
            As[la_k + 2][la_m] = 0.f; As[la_k + 3][la_m] = 0.f;
        }
        {
            float4 v = *reinterpret_cast<const float4*>(W + (size_t)(k0 + lw_k) * Nc + n0 + lw_n);
            *reinterpret_cast<float4*>(&Ws[lw_k][lw_n]) = v;
        }
        __syncthreads();
        #pragma unroll
        for (int kk = 0; kk < BK; kk++) {
            float4 ra = *reinterpret_cast<const float4*>(&As[kk][ty * 4]);
            float4 rb = *reinterpret_cast<const float4*>(&Ws[kk][tx * 4]);
            float a[4] = {ra.x, ra.y, ra.z, ra.w};
            float b[4] = {rb.x, rb.y, rb.z, rb.w};
            #pragma unroll
            for (int i = 0; i < 4; i++)
                #pragma unroll
                for (int j = 0; j < 4; j++)
                    acc[i][j] += a[i] * b[j];
        }
        __syncthreads();
    }
    #pragma unroll
    for (int i = 0; i < 4; i++) {
        int row = m0 + ty * 4 + i;
        if (row >= M) continue;
        #pragma unroll
        for (int j = 0; j < 4; j++) {
            int col = n0 + tx * 4 + j;
            float v = acc[i][j];
            if (FLAGS & 1) v += bias[col];
            if (FLAGS & 2) v = gelu_f(v);
            if (FLAGS & 4) v += Res[(size_t)row * Nc + col];
            C[(size_t)row * Nc + col] = v;
        }
    }
}

// ---------------- graph prep ----------------
__global__ void deg_init_k() {
    int i = blockIdx.x * blockDim.x + threadIdx.x;
    if (i < NN) { g_deg[i] = 1.0f; g_icnt[i] = 0; }
    if (i < GG) g_cnt[i] = 0.0f;
}
__global__ void deg_edge_k(const int* __restrict__ dst) {
    int e = blockIdx.x * blockDim.x + threadIdx.x;
    if (e < NE) {
        int d = dst[e];
        atomicAdd(&g_deg[d], 1.0f);
        atomicAdd(&g_icnt[d], 1);
    }
}
__global__ void dinv_cnt_k(const int* __restrict__ batch) {
    int i = blockIdx.x * blockDim.x + threadIdx.x;
    if (i < NN) {
        g_dinv[i] = rsqrtf(g_deg[i]);
        atomicAdd(&g_cnt[batch[i]], 1.0f);
    }
}
// ---- CSR scan ----
__global__ void scan1_k() {
    __shared__ int sh[256];
    int i = blockIdx.x * 256 + threadIdx.x;
    int v = (i < NN) ? g_icnt[i] : 0;
    sh[threadIdx.x] = v;
    __syncthreads();
    for (int o = 1; o < 256; o <<= 1) {
        int tv = (threadIdx.x >= o) ? sh[threadIdx.x - o] : 0;
        __syncthreads();
        sh[threadIdx.x] += tv;
        __syncthreads();
    }
    if (i < NN) g_scan[i] = sh[threadIdx.x] - v;
    if (threadIdx.x == 255) g_bsum[blockIdx.x] = sh[255];
}
__global__ void scan2_k(int nb) {
    __shared__ int sh[512];
    int t = threadIdx.x;
    int v = (t < nb) ? g_bsum[t] : 0;
    sh[t] = v;
    __syncthreads();
    for (int o = 1; o < 512; o <<= 1) {
        int tv = (t >= o) ? sh[t - o] : 0;
        __syncthreads();
        sh[t] += tv;
        __syncthreads();
    }
    if (t < nb) g_bsum[t] = sh[t] - v;
}
__global__ void scan3_k() {
    int i = blockIdx.x * blockDim.x + threadIdx.x;
    if (i < NN) {
        int rp = g_scan[i] + g_bsum[i >> 8];
        g_rowptr[i] = rp;
        g_fill[i] = rp;
    }
    if (i == 0) g_rowptr[NN] = NE;
}
__global__ void scatter_k(const int* __restrict__ src, const int* __restrict__ dst) {
    int e = blockIdx.x * blockDim.x + threadIdx.x;
    if (e < NE) {
        int pos = atomicAdd(&g_fill[dst[e]], 1);
        g_ecol[pos] = src[e];
    }
}

// ---------------- per-hop elementwise (8 elems/thread, 16B accesses) ----------------
__global__ void vn_init_k(const float* __restrict__ vn_emb) {
    int i = blockIdx.x * blockDim.x + threadIdx.x;
    if (i < GG * HH) g_vn[i] = vn_emb[i & (HH - 1)];
}
__device__ __forceinline__ void unpack8(uint4 h, uint4 l, float* v) {
    __half2 h0 = *reinterpret_cast<__half2*>(&h.x), h1 = *reinterpret_cast<__half2*>(&h.y);
    __half2 h2 = *reinterpret_cast<__half2*>(&h.z), h3 = *reinterpret_cast<__half2*>(&h.w);
    __half2 l0 = *reinterpret_cast<__half2*>(&l.x), l1 = *reinterpret_cast<__half2*>(&l.y);
    __half2 l2 = *reinterpret_cast<__half2*>(&l.z), l3 = *reinterpret_cast<__half2*>(&l.w);
    v[0] = __low2float(h0) + __low2float(l0);  v[1] = __high2float(h0) + __high2float(l0);
    v[2] = __low2float(h1) + __low2float(l1);  v[3] = __high2float(h1) + __high2float(l1);
    v[4] = __low2float(h2) + __low2float(l2);  v[5] = __high2float(h2) + __high2float(l2);
    v[6] = __low2float(h3) + __low2float(l3);  v[7] = __high2float(h3) + __high2float(l3);
}
__device__ __forceinline__ void pack8(const float* v, uint4& h, uint4& l) {
    __half a0 = __float2half_rn(v[0]), a1 = __float2half_rn(v[1]);
    __half a2 = __float2half_rn(v[2]), a3 = __float2half_rn(v[3]);
    __half a4 = __float2half_rn(v[4]), a5 = __float2half_rn(v[5]);
    __half a6 = __float2half_rn(v[6]), a7 = __float2half_rn(v[7]);
    __half2 p;
    p = __halves2half2(a0, a1); h.x = *reinterpret_cast<uint32_t*>(&p);
    p = __halves2half2(a2, a3); h.y = *reinterpret_cast<uint32_t*>(&p);
    p = __halves2half2(a4, a5); h.z = *reinterpret_cast<uint32_t*>(&p);
    p = __halves2half2(a6, a7); h.w = *reinterpret_cast<uint32_t*>(&p);
    p = __floats2half2_rn(v[0] - __half2float(a0), v[1] - __half2float(a1));
    l.x = *reinterpret_cast<uint32_t*>(&p);
    p = __floats2half2_rn(v[2] - __half2float(a2), v[3] - __half2float(a3));
    l.y = *reinterpret_cast<uint32_t*>(&p);
    p = __floats2half2_rn(v[4] - __half2float(a4), v[5] - __half2float(a5));
    l.z = *reinterpret_cast<uint32_t*>(&p);
    p = __floats2half2_rn(v[6] - __half2float(a6), v[7] - __half2float(a7));
    l.w = *reinterpret_cast<uint32_t*>(&p);
}
// x += vn[batch]; 8 elems/thread; block 0 zeros BN accumulators
__global__ void addvn_split_k(const int* __restrict__ batch) {
    int i = blockIdx.x * blockDim.x + threadIdx.x;   // over EW/8
    if (blockIdx.x == 0 && threadIdx.x < HH) {
        g_sum[threadIdx.x] = 0.0; g_sumsq[threadIdx.x] = 0.0;
    }
    if (i < NN * HH / 8) {
        int r  = i >> 4;          // 16 chunks of 8 per row
        int c8 = (i & 15) * 8;
        uint4* ph = reinterpret_cast<uint4*>(g_ahi) + i;
        uint4* pl = reinterpret_cast<uint4*>(g_alo) + i;
        uint4 hv = *ph, lv = *pl;
        float v[8];
        unpack8(hv, lv, v);
        const float* vnp = g_vn + batch[r] * HH + c8;
        float4 vn0 = *reinterpret_cast<const float4*>(vnp);
        float4 vn1 = *reinterpret_cast<const float4*>(vnp + 4);
        v[0] += vn0.x; v[1] += vn0.y; v[2] += vn0.z; v[3] += vn0.w;
        v[4] += vn1.x; v[5] += vn1.y; v[6] += vn1.z; v[7] += vn1.w;
        pack8(v, hv, lv);
        *ph = hv; *pl = lv;
    }
}
// CSR gather + conv bias + residual(split) + fp64 BN stats with block-reduced atomics
__global__ void gcn_gather_bn_k(const float* __restrict__ bias) {
    __shared__ double s_sum[HH], s_sq[HH];
    int t = threadIdx.x;
    if (t < HH) { s_sum[t] = 0.0; s_sq[t] = 0.0; }
    __syncthreads();

    int gtid = blockIdx.x * blockDim.x + t;
    int warp = gtid >> 5, lane = gtid & 31;
    int nw = (gridDim.x * blockDim.x) >> 5;
    float4 b4 = *reinterpret_cast<const float4*>(bias + lane * 4);
    double s0 = 0, s1 = 0, s2 = 0, s3 = 0, q0 = 0, q1 = 0, q2 = 0, q3 = 0;
    for (int n = warp; n < NN; n += nw) {
        float di = g_dinv[n];
        size_t rb = (size_t)n * HH + lane * 4;
        float4 hv = *reinterpret_cast<const float4*>(g_h + rb);
        float sl = di * di;
        float ax = hv.x * sl, ay = hv.y * sl, az = hv.z * sl, aw = hv.w * sl;
        int e0 = g_rowptr[n], e1 = g_rowptr[n + 1];
        #pragma unroll 4
        for (int e = e0; e < e1; e++) {
            int sI = g_ecol[e];
            float nrm = g_dinv[sI] * di;
            float4 v = *reinterpret_cast<const float4*>(g_h + (size_t)sI * HH + lane * 4);
            ax += v.x * nrm; ay += v.y * nrm; az += v.z * nrm; aw += v.w * nrm;
        }
        __half2 xh0 = *reinterpret_cast<const __half2*>(g_ahi + rb);
        __half2 xh1 = *reinterpret_cast<const __half2*>(g_ahi + rb + 2);
        __half2 xl0 = *reinterpret_cast<const __half2*>(g_alo + rb);
        __half2 xl1 = *reinterpret_cast<const __half2*>(g_alo + rb + 2);
        float t0 = ax + b4.x + __low2float(xh0)  + __low2float(xl0);
        float t1 = ay + b4.y + __high2float(xh0) + __high2float(xl0);
        float t2 = az + b4.z + __low2float(xh1)  + __low2float(xl1);
        float t3 = aw + b4.w + __high2float(xh1) + __high2float(xl1);
        __half h0 = __float2half_rn(t0), h1 = __float2half_rn(t1);
        __half h2 = __float2half_rn(t2), h3 = __float2half_rn(t3);
        *reinterpret_cast<__half2*>(g_ahi + rb)     = __halves2half2(h0, h1);
        *reinterpret_cast<__half2*>(g_ahi + rb + 2) = __halves2half2(h2, h3);
        *reinterpret_cast<__half2*>(g_alo + rb) = __floats2half2_rn(
            t0 - __half2float(h0), t1 - __half2float(h1));
        *reinterpret_cast<__half2*>(g_alo + rb + 2) = __floats2half2_rn(
            t2 - __half2float(h2), t3 - __half2float(h3));
        s0 += t0; s1 += t1; s2 += t2; s3 += t3;
        q0 += (double)t0 * t0; q1 += (double)t1 * t1;
        q2 += (double)t2 * t2; q3 += (double)t3 * t3;
    }
    atomicAdd(&s_sum[lane * 4 + 0], s0); atomicAdd(&s_sq[lane * 4 + 0], q0);
    atomicAdd(&s_sum[lane * 4 + 1], s1); atomicAdd(&s_sq[lane * 4 + 1], q1);
    atomicAdd(&s_sum[lane * 4 + 2], s2); atomicAdd(&s_sq[lane * 4 + 2], q2);
    atomicAdd(&s_sum[lane * 4 + 3], s3); atomicAdd(&s_sq[lane * 4 + 3], q3);
    __syncthreads();
    if (t < HH) {
        atomicAdd(&g_sum[t],   s_sum[t]);
        atomicAdd(&g_sumsq[t], s_sq[t]);
    }
}
// tiny single-block fp64 finalize -> fp32 scale/shift
__global__ void bn_final_k(const float* __restrict__ gam, const float* __restrict__ bet) {
    int f = threadIdx.x;
    double mean = g_sum[f] / (double)NN;
    double var  = g_sumsq[f] / (double)NN - mean * mean;
    float a = gam[f] * rsqrtf((float)var + EPSV);
    g_bnA[f] = a;
    g_bnC[f] = bet[f] - (float)mean * a;
}
// BN apply, 8 elems/thread; block 0 zeros g_pool
__global__ void bn_apply_split_k() {
    if (blockIdx.x == 0) {
        for (int p = threadIdx.x; p < GG * HH; p += 256) g_pool[p] = 0.0f;
    }
    int i = blockIdx.x * blockDim.x + threadIdx.x;   // over EW/8
    if (i < NN * HH / 8) {
        int c8 = (i & 15) * 8;
        uint4* ph = reinterpret_cast<uint4*>(g_ahi) + i;
        uint4* pl = reinterpret_cast<uint4*>(g_alo) + i;
        uint4 hv = *ph, lv = *pl;
        float v[8];
        unpack8(hv, lv, v);
        float4 A0 = *reinterpret_cast<const float4*>(g_bnA + c8);
        float4 A1 = *reinterpret_cast<const float4*>(g_bnA + c8 + 4);
        float4 C0 = *reinterpret_cast<const float4*>(g_bnC + c8);
        float4 C1 = *reinterpret_cast<const float4*>(g_bnC + c8 + 4);
        v[0] = v[0] * A0.x + C0.x; v[1] = v[1] * A0.y + C0.y;
        v[2] = v[2] * A0.z + C0.z; v[3] = v[3] * A0.w + C0.w;
        v[4] = v[4] * A1.x + C1.x; v[5] = v[5] * A1.y + C1.y;
        v[6] = v[6] * A1.z + C1.z; v[7] = v[7] * A1.w + C1.w;
        pack8(v, hv, lv);
        *ph = hv; *pl = lv;
    }
}

// ---------------- pooling (uint4: 16 lanes x 16 row-subranges per block) ----------------
#define PROWS 128
__global__ void pool_k(const int* __restrict__ batch) {
    int lane = threadIdx.x & 15;          // features 8*lane .. 8*lane+7
    int sub  = threadIdx.x >> 4;          // 0..15
    int r0 = blockIdx.x * PROWS + sub * 8;
    if (r0 >= NN) return;
    int r1 = min(r0 + 8, NN);
    float a[8] = {0.f, 0.f, 0.f, 0.f, 0.f, 0.f, 0.f, 0.f};
    int cur = batch[r0];
    for (int r = r0; r < r1; r++) {
        int g = batch[r];
        if (g != cur) {
            float* pp = &g_pool[cur * HH + lane * 8];
            #pragma unroll
            for (int j = 0; j < 8; j++) { atomicAdd(pp + j, a[j]); a[j] = 0.f; }
            cur = g;
        }
        size_t idx = (size_t)r * HH + lane * 8;
        uint4 hv = *reinterpret_cast<const uint4*>(g_ahi + idx);
        uint4 lv = *reinterpret_cast<const uint4*>(g_alo + idx);
        float v[8];
        unpack8(hv, lv, v);
        #pragma unroll
        for (int j = 0; j < 8; j++) a[j] += v[j];
    }
    float* pp = &g_pool[cur * HH + lane * 8];
    #pragma unroll
    for (int j = 0; j < 8; j++) atomicAdd(pp + j, a[j]);
}
__global__ void vn_mlp1_k(const float* __restrict__ W1, const float* __restrict__ b1,
                          const float* __restrict__ g1, const float* __restrict__ be1) {
    int f = blockIdx.x;
    int g = threadIdx.x;
    float ic = 1.0f / fmaxf(g_cnt[g], 1.0f);
    float acc = b1[f];
    #pragma unroll 4
    for (int k = 0; k < HH; k++) {
        float vnk = g_vn[g * HH + k] + g_pool[g * HH + k] * ic;
        acc += vnk * W1[k * H2 + f];
    }
    __shared__ float sh[64], sh2[64];
    sh[g] = acc; sh2[g] = acc * acc;
    __syncthreads();
    for (int o = 32; o > 0; o >>= 1) {
        if (g < o) { sh[g] += sh[g + o]; sh2[g] += sh2[g + o]; }
        __syncthreads();
    }
    float mean = sh[0] * (1.0f / 64.0f);
    float var  = sh2[0] * (1.0f / 64.0f) - mean * mean;
    float a = g1[f] * rsqrtf(var + EPSV);
    float c = be1[f] - mean * a;
    g_vnh[g * H2 + f] = gelu_f(acc * a + c);
}
__global__ void vn_mlp2_k(const float* __restrict__ W2, const float* __restrict__ b2,
                          const float* __restrict__ g2, const float* __restrict__ be2) {
    int f = blockIdx.x;
    int g = threadIdx.x;
    float acc = b2[f];
    #pragma unroll 4
    for (int k = 0; k < H2; k++)
        acc += g_vnh[g * H2 + k] * W2[k * HH + f];
    __shared__ float sh[64], sh2[64];
    sh[g] = acc; sh2[g] = acc * acc;
    __syncthreads();
    for (int o = 32; o > 0; o >>= 1) {
        if (g < o) { sh[g] += sh[g + o]; sh2[g] += sh2[g + o]; }
        __syncthreads();
    }
    float mean = sh[0] * (1.0f / 64.0f);
    float var  = sh2[0] * (1.0f / 64.0f) - mean * mean;
    float a = g2[f] * rsqrtf(var + EPSV);
    float c = be2[f] - mean * a;
    g_vn[g * HH + f] = gelu_f(acc * a + c);
}

// ---------------- host ----------------
extern "C" void kernel_launch(void* const* d_in, const int* in_sizes, int n_in,
                              void* d_out, int out_size)
{
    const float* x_in   = (const float*)d_in[0];
    const int*   ei     = (const int*)  d_in[1];
    const int*   batch  = (const int*)  d_in[2];
    const float* pre_W1 = (const float*)d_in[3];
    const float* pre_b1 = (const float*)d_in[4];
    const float* pre_W2 = (const float*)d_in[5];
    const float* pre_b2 = (const float*)d_in[6];
    const float* conv_W = (const float*)d_in[7];
    const float* conv_b = (const float*)d_in[8];
    const float* bn_g   = (const float*)d_in[9];
    const float* bn_b   = (const float*)d_in[10];
    const float* ffn_W1 = (const float*)d_in[11];
    const float* ffn_b1 = (const float*)d_in[12];
    const float* ffn_W2 = (const float*)d_in[13];
    const float* ffn_b2 = (const float*)d_in[14];
    const float* vn_W1  = (const float*)d_in[15];
    const float* vn_b1  = (const float*)d_in[16];
    const float* vn_g1  = (const float*)d_in[17];
    const float* vn_be1 = (const float*)d_in[18];
    const float* vn_W2  = (const float*)d_in[19];
    const float* vn_b2  = (const float*)d_in[20];
    const float* vn_g2  = (const float*)d_in[21];
    const float* vn_be2 = (const float*)d_in[22];
    const float* vn_emb = (const float*)d_in[23];
    const float* post_W1= (const float*)d_in[24];
    const float* post_b1= (const float*)d_in[25];
    const float* post_W2= (const float*)d_in[26];
    const float* post_b2= (const float*)d_in[27];
    float* out = (float*)d_out;

    const int* src = ei;
    const int* dst = ei + NE;

    float *ph, *ppool, *pvnh;
    __half *pahi, *palo, *phhi, *phlo, *pwhi, *pwlo;
    cudaGetSymbolAddress((void**)&ph,   g_h);
    cudaGetSymbolAddress((void**)&ppool,g_pool);
    cudaGetSymbolAddress((void**)&pvnh, g_vnh);
    cudaGetSymbolAddress((void**)&pahi, g_ahi);
    cudaGetSymbolAddress((void**)&palo, g_alo);
    cudaGetSymbolAddress((void**)&phhi, g_hhi);
    cudaGetSymbolAddress((void**)&phlo, g_hlo);
    cudaGetSymbolAddress((void**)&pwhi, g_whi);
    cudaGetSymbolAddress((void**)&pwlo, g_wlo);

    cudaFuncSetAttribute(mma_gemm<11>, cudaFuncAttributeMaxDynamicSharedMemorySize, GSMEM);
    cudaFuncSetAttribute(mma_gemm<15>, cudaFuncAttributeMaxDynamicSharedMemorySize, GSMEM);
    cudaFuncSetAttribute(mma_gemm<16>, cudaFuncAttributeMaxDynamicSharedMemorySize, GSMEM);

    const int EW = NN * HH;
    dim3 blk(256);
    int gEW4 = (EW / 4 + 255) / 256;
    int gEW8 = (EW / 8 + 255) / 256;
    const int MT = (NN + 127) / 128;   // 782
    const int NB = (NN + 255) / 256;   // 391

    // launches 1-3, then #4 = mma_gemm<11> (pre1) — ncu -s 5 with 2 harness launches
    wprep_all_k<<<(WTOT + 255) / 256, blk>>>(pre_W1, pre_W2, conv_W, ffn_W1, ffn_W2); // 1
    split_k<<<gEW4, blk>>>(x_in, pahi, palo, EW / 4);                                 // 2
    deg_init_k<<<NB, blk>>>();                                                        // 3
    mma_gemm<11><<<dim3(4, MT), 256, GSMEM>>>(pahi, palo, pwhi + OW_PRE1, pwlo + OW_PRE1,
        pre_b1, nullptr, nullptr, nullptr, phhi, phlo, NN, HH, H2);                   // 4 <- ncu
    deg_edge_k<<<(NE + 255) / 256, blk>>>(dst);
    dinv_cnt_k<<<NB, blk>>>(batch);
    scan1_k<<<NB, blk>>>();
    scan2_k<<<1, 512>>>(NB);
    scan3_k<<<NB, blk>>>();
    scatter_k<<<(NE + 255) / 256, blk>>>(src, dst);
    // pre2: x = gelu(hid@pre_W2+b) -> splits (ahi/alo)
    mma_gemm<11><<<dim3(2, MT), 256, GSMEM>>>(phhi, phlo, pwhi + OW_PRE2, pwlo + OW_PRE2,
        pre_b2, nullptr, nullptr, nullptr, pahi, palo, NN, H2, HH);
    vn_init_k<<<(GG * HH + 255) / 256, blk>>>(vn_emb);

    for (int i = 0; i < NHOPS; i++) {
        addvn_split_k<<<gEW8, blk>>>(batch);
        // h = x @ conv_W[i]  (fp32 out, gather-friendly)
        mma_gemm<16><<<dim3(2, MT), 256, GSMEM>>>(pahi, palo, pwhi + OW_CONV(i), pwlo + OW_CONV(i),
            nullptr, nullptr, nullptr, ph, nullptr, nullptr, NN, HH, HH);
        gcn_gather_bn_k<<<512, 256>>>(conv_b + (size_t)i * HH);
        bn_final_k<<<1, HH>>>(bn_g + (size_t)i * HH, bn_b + (size_t)i * HH);
        bn_apply_split_k<<<gEW8, blk>>>();
        // hid = gelu(x@ffn_W1+b) -> splits
        mma_gemm<11><<<dim3(4, MT), 256, GSMEM>>>(pahi, palo, pwhi + OW_FFN1(i), pwlo + OW_FFN1(i),
            ffn_b1 + (size_t)i * H2, nullptr, nullptr, nullptr, phhi, phlo, NN, HH, H2);
        // x = gelu(hid@ffn_W2+b) + x  -> splits (in-place residual)
        mma_gemm<15><<<dim3(2, MT), 256, GSMEM>>>(phhi, phlo, pwhi + OW_FFN2(i), pwlo + OW_FFN2(i),
            ffn_b2 + (size_t)i * HH, pahi, palo, nullptr, pahi, palo, NN, H2, HH);
        if (i < NHOPS - 1) {
            pool_k<<<(NN + PROWS - 1) / PROWS, blk>>>(batch);
            vn_mlp1_k<<<H2, GG>>>(vn_W1 + (size_t)i * HH * H2, vn_b1 + (size_t)i * H2,
                                  vn_g1 + (size_t)i * H2, vn_be1 + (size_t)i * H2);
            vn_mlp2_k<<<HH, GG>>>(vn_W2 + (size_t)i * H2 * HH, vn_b2 + (size_t)i * HH,
                                  vn_g2 + (size_t)i * HH, vn_be2 + (size_t)i * HH);
        }
    }

    // ---- final pool + post-FFNN (fp32) ----
    pool_k<<<(NN + PROWS - 1) / PROWS, blk>>>(batch);
    dim3 gp1(H2 / 64, 1);
    gemm64<3><<<gp1, blk>>>(ppool, post_W1, post_b1, nullptr, pvnh, GG, HH, H2);
    dim3 gp2(HH / 64, 1);
    gemm64<3><<<gp2, blk>>>(pvnh, post_W2, post_b2, nullptr, out, GG, H2, HH);
}

// round 17
// speedup vs baseline: 1.0339x; 1.0339x over previous
#include <cuda_runtime.h>
#include <cuda_fp16.h>
#include <math.h>
#include <cstdint>

#define NN 100000
#define NE 625000
#define HH 128
#define H2 256
#define GG 64
#define NHOPS 5
#define EPSV 1e-5f

// ---------------- scratch (static device globals; no allocation) ----------------
static __device__ float  g_h  [(size_t)NN * HH];
static __device__ float  g_deg [NN];
static __device__ float  g_dinv[NN];
static __device__ float  g_vn  [GG * HH];
static __device__ float  g_vnh [GG * H2];
static __device__ float  g_pool[GG * HH];
static __device__ float  g_cnt [GG];
static __device__ double g_sum  [HH];
static __device__ double g_sumsq[HH];
static __device__ float  g_bnA[HH];
static __device__ float  g_bnC[HH];
static __device__ int    g_barrier;
// CSR
static __device__ int g_icnt[NN];
static __device__ int g_scan[NN];
static __device__ int g_bsum[512];
static __device__ int g_rowptr[NN + 1];
static __device__ int g_fill[NN];
static __device__ int g_ecol[NE];
// fp16 hi/lo split buffers: x lives ONLY as (ahi+alo); hidden as (hhi+hlo)
static __device__ __half g_ahi[(size_t)NN * HH];
static __device__ __half g_alo[(size_t)NN * HH];
static __device__ __half g_hhi[(size_t)NN * H2];
static __device__ __half g_hlo[(size_t)NN * H2];
// transposed + split weights: [N,K] row-major fp16 hi/lo
#define WTOT 475136
static __device__ __half g_whi[WTOT];
static __device__ __half g_wlo[WTOT];
#define OW_PRE1 0
#define OW_PRE2 32768
#define OW_CONV(i) (65536 + (i) * 16384)
#define OW_FFN1(i) (147456 + (i) * 32768)
#define OW_FFN2(i) (311296 + (i) * 32768)

__device__ __forceinline__ float gelu_f(float x) {
    return 0.5f * x * (1.0f + erff(x * 0.70710678118654752f));
}
__device__ __forceinline__ uint32_t smem_u32(const void* p) {
    uint32_t a;
    asm("{ .reg .u64 t; cvta.to.shared.u64 t, %1; cvt.u32.u64 %0, t; }" : "=r"(a) : "l"(p));
    return a;
}
__device__ __forceinline__ void ldsm4(uint32_t& r0, uint32_t& r1, uint32_t& r2, uint32_t& r3,
                                      uint32_t addr) {
    asm volatile("ldmatrix.sync.aligned.m8n8.x4.shared.b16 {%0,%1,%2,%3}, [%4];"
                 : "=r"(r0), "=r"(r1), "=r"(r2), "=r"(r3) : "r"(addr));
}
__device__ __forceinline__ void mma_f16(float* c, uint32_t a0, uint32_t a1, uint32_t a2,
                                        uint32_t a3, uint32_t b0, uint32_t b1) {
    asm volatile("mma.sync.aligned.m16n8k16.row.col.f32.f16.f16.f32 "
                 "{%0,%1,%2,%3}, {%4,%5,%6,%7}, {%8,%9}, {%0,%1,%2,%3};"
                 : "+f"(c[0]), "+f"(c[1]), "+f"(c[2]), "+f"(c[3])
                 : "r"(a0), "r"(a1), "r"(a2), "r"(a3), "r"(b0), "r"(b1));
}
__device__ __forceinline__ void cp16(uint32_t dst, const void* src, int sz) {
    asm volatile("cp.async.cg.shared.global [%0], [%1], 16, %2;"
                 :: "r"(dst), "l"(src), "r"(sz) : "memory");
}
// L1-cached variant for weight (B) tiles
__device__ __forceinline__ void cp16ca(uint32_t dst, const void* src) {
    asm volatile("cp.async.ca.shared.global [%0], [%1], 16;"
                 :: "r"(dst), "l"(src) : "memory");
}
#define CP_COMMIT() asm volatile("cp.async.commit_group;" ::: "memory")
#define CP_WAIT(n)  asm volatile("cp.async.wait_group %0;" :: "n"(n) : "memory")

// ==== 3-term fp16 GEMM: CTA 128x64, warp 32x32, 3 CTAs/SM ====
// FLAGS: 1=+bias 2=gelu 4=+Res(from split) 8=write hi/lo split 16=write fp32 C
#define KC 32
#define ROWB 80
#define ABUF (128 * ROWB)
#define BBUF (64 * ROWB)
#define STGB (2 * ABUF + 2 * BBUF)   // 30720
#define GSMEM (2 * STGB)             // 61440

template <int FLAGS>
__global__ void __launch_bounds__(256, 3) mma_gemm(
    const __half* __restrict__ Ahi, const __half* __restrict__ Alo,
    const __half* __restrict__ Bhi, const __half* __restrict__ Blo,
    const float* __restrict__ bias,
    const __half* __restrict__ Reshi, const __half* __restrict__ Reslo,
    float* __restrict__ C, __half* __restrict__ Chi, __half* __restrict__ Clo,
    int M, int K, int Nc)
{
    extern __shared__ char sm[];
    uint32_t sb = smem_u32(sm);

    int t = threadIdx.x;
    int lid = t & 31, wid = t >> 5;
    int wm = wid & 3, wn = wid >> 2;
    int m0 = blockIdx.y * 128, n0 = blockIdx.x * 64;
    int nchunks = K / KC;

    float acc[2][4][4];
    #pragma unroll
    for (int i = 0; i < 2; i++)
        #pragma unroll
        for (int j = 0; j < 4; j++)
            #pragma unroll
            for (int k = 0; k < 4; k++) acc[i][j][k] = 0.f;

    auto issue = [&](int ch) {
        uint32_t st = sb + (uint32_t)(ch & 1) * STGB;
        int k0 = ch * KC;
        #pragma unroll
        for (int i = 0; i < 2; i++) {
            int c = t + i * 256;
            int r = c >> 2;
            int kcEl = (c & 3) * 8;
            uint32_t doff = (uint32_t)r * ROWB + (uint32_t)kcEl * 2;
            int ar = m0 + r;
            int okA = (ar < M) ? 16 : 0;
            int arc = okA ? ar : 0;
            cp16(st + doff,        Ahi + (size_t)arc * K + k0 + kcEl, okA);
            cp16(st + ABUF + doff, Alo + (size_t)arc * K + k0 + kcEl, okA);
        }
        {
            int c = t;
            int r = c >> 2;
            int kcEl = (c & 3) * 8;
            uint32_t doff = (uint32_t)r * ROWB + (uint32_t)kcEl * 2;
            int br = n0 + r;
            cp16ca(st + 2 * ABUF + doff,        Bhi + (size_t)br * K + k0 + kcEl);
            cp16ca(st + 2 * ABUF + BBUF + doff, Blo + (size_t)br * K + k0 + kcEl);
        }
        CP_COMMIT();
    };

    issue(0);
    for (int ch = 0; ch < nchunks; ch++) {
        if (ch + 1 < nchunks) { issue(ch + 1); CP_WAIT(1); }
        else                  { CP_WAIT(0); }
        __syncthreads();

        uint32_t st  = sb + (uint32_t)(ch & 1) * STGB;
        uint32_t sAh = st, sAl = st + ABUF;
        uint32_t sBh = st + 2 * ABUF, sBl = st + 2 * ABUF + BBUF;

        #pragma unroll
        for (int ks = 0; ks < 2; ks++) {
            int kk = ks * 16;
            uint32_t ah[2][4], al[2][4];
            #pragma unroll
            for (int mr = 0; mr < 2; mr++) {
                int row = wm * 32 + mr * 16 + (lid & 15);
                uint32_t off = (uint32_t)row * ROWB + ((uint32_t)kk + (lid >> 4) * 8) * 2;
                ldsm4(ah[mr][0], ah[mr][1], ah[mr][2], ah[mr][3], sAh + off);
                ldsm4(al[mr][0], al[mr][1], al[mr][2], al[mr][3], sAl + off);
            }
            uint32_t bh[2][4], bl[2][4];
            #pragma unroll
            for (int np = 0; np < 2; np++) {
                int brow = wn * 32 + np * 16 + (lid & 7) + ((lid >> 4) & 1) * 8;
                uint32_t off = (uint32_t)brow * ROWB + ((uint32_t)kk + ((lid >> 3) & 1) * 8) * 2;
                ldsm4(bh[np][0], bh[np][1], bh[np][2], bh[np][3], sBh + off);
                ldsm4(bl[np][0], bl[np][1], bl[np][2], bl[np][3], sBl + off);
            }
            #pragma unroll
            for (int np = 0; np < 2; np++)
                #pragma unroll
                for (int mr = 0; mr < 2; mr++) {
                    mma_f16(acc[mr][np * 2],     ah[mr][0], ah[mr][1], ah[mr][2], ah[mr][3],
                            bh[np][0], bh[np][1]);
                    mma_f16(acc[mr][np * 2 + 1], ah[mr][0], ah[mr][1], ah[mr][2], ah[mr][3],
                            bh[np][2], bh[np][3]);
                }
            #pragma unroll
            for (int np = 0; np < 2; np++)
                #pragma unroll
                for (int mr = 0; mr < 2; mr++) {
                    mma_f16(acc[mr][np * 2],     al[mr][0], al[mr][1], al[mr][2], al[mr][3],
                            bh[np][0], bh[np][1]);
                    mma_f16(acc[mr][np * 2 + 1], al[mr][0], al[mr][1], al[mr][2], al[mr][3],
                            bh[np][2], bh[np][3]);
                }
            #pragma unroll
            for (int np = 0; np < 2; np++)
                #pragma unroll
                for (int mr = 0; mr < 2; mr++) {
                    mma_f16(acc[mr][np * 2],     ah[mr][0], ah[mr][1], ah[mr][2], ah[mr][3],
                            bl[np][0], bl[np][1]);
                    mma_f16(acc[mr][np * 2 + 1], ah[mr][0], ah[mr][1], ah[mr][2], ah[mr][3],
                            bl[np][2], bl[np][3]);
                }
        }
        __syncthreads();
    }

    // vectorized epilogue: (col,col+1) pairs
    #pragma unroll
    for (int mr = 0; mr < 2; mr++) {
        #pragma unroll
        for (int nc = 0; nc < 4; nc++) {
            int col = n0 + wn * 32 + nc * 8 + (lid & 3) * 2;
            #pragma unroll
            for (int hf = 0; hf < 2; hf++) {
                int row = m0 + wm * 32 + mr * 16 + (lid >> 2) + hf * 8;
                if (row >= M) continue;
                float v0 = acc[mr][nc][hf * 2 + 0];
                float v1 = acc[mr][nc][hf * 2 + 1];
                if (FLAGS & 1) { v0 += bias[col]; v1 += bias[col + 1]; }
                if (FLAGS & 2) { v0 = gelu_f(v0); v1 = gelu_f(v1); }
                size_t gidx = (size_t)row * Nc + col;
                if (FLAGS & 4) {
                    __half2 rh = *reinterpret_cast<const __half2*>(Reshi + gidx);
                    __half2 rl = *reinterpret_cast<const __half2*>(Reslo + gidx);
                    v0 += __low2float(rh)  + __low2float(rl);
                    v1 += __high2float(rh) + __high2float(rl);
                }
                if (FLAGS & 16)
                    *reinterpret_cast<float2*>(C + gidx) = make_float2(v0, v1);
                if (FLAGS & 8) {
                    __half h0 = __float2half_rn(v0), h1 = __float2half_rn(v1);
                    *reinterpret_cast<__half2*>(Chi + gidx) = __halves2half2(h0, h1);
                    *reinterpret_cast<__half2*>(Clo + gidx) = __floats2half2_rn(
                        v0 - __half2float(h0), v1 - __half2float(h1));
                }
            }
        }
    }
}

// ======================= fused weight prep (fp16 hi/lo, transposed) =======================
__global__ void wprep_all_k(const float* __restrict__ pre_W1, const float* __restrict__ pre_W2,
                            const float* __restrict__ conv_W, const float* __restrict__ ffn_W1,
                            const float* __restrict__ ffn_W2) {
    int i = blockIdx.x * blockDim.x + threadIdx.x;
    if (i >= WTOT) return;
    const float* src; int K, Nc, off;
    if (i < 32768)       { src = pre_W1; K = HH; Nc = H2; off = i; }
    else if (i < 65536)  { src = pre_W2; K = H2; Nc = HH; off = i - 32768; }
    else if (i < 147456) { int l = (i - 65536) >> 14; src = conv_W + l * 16384;
                           K = HH; Nc = HH; off = (i - 65536) & 16383; }
    else if (i < 311296) { int l = (i - 147456) >> 15; src = ffn_W1 + (size_t)l * 32768;
                           K = HH; Nc = H2; off = (i - 147456) & 32767; }
    else                 { int l = (i - 311296) >> 15; src = ffn_W2 + (size_t)l * 32768;
                           K = H2; Nc = HH; off = (i - 311296) & 32767; }
    int n = off / K, k = off - n * K;
    float v = src[(size_t)k * Nc + n];
    __half h = __float2half_rn(v);
    g_whi[i] = h;
    g_wlo[i] = __float2half_rn(v - __half2float(h));
}
// split input x (4 elems/thread)
__global__ void split_k(const float* __restrict__ X, __half* __restrict__ hi,
                        __half* __restrict__ lo, int n4) {
    int i = blockIdx.x * blockDim.x + threadIdx.x;
    if (i >= n4) return;
    float4 v = reinterpret_cast<const float4*>(X)[i];
    __half h0 = __float2half_rn(v.x), h1 = __float2half_rn(v.y);
    __half h2 = __float2half_rn(v.z), h3 = __float2half_rn(v.w);
    reinterpret_cast<__half2*>(hi)[i * 2]     = __halves2half2(h0, h1);
    reinterpret_cast<__half2*>(hi)[i * 2 + 1] = __halves2half2(h2, h3);
    reinterpret_cast<__half2*>(lo)[i * 2]     = __floats2half2_rn(
        v.x - __half2float(h0), v.y - __half2float(h1));
    reinterpret_cast<__half2*>(lo)[i * 2 + 1] = __floats2half2_rn(
        v.z - __half2float(h2), v.w - __half2float(h3));
}

// ---------------- small SIMT GEMM (final post-FFNN, G=64 rows) ----------------
template <int FLAGS>
__global__ void gemm64(const float* __restrict__ A, const float* __restrict__ W,
                       const float* __restrict__ bias, const float* __restrict__ Res,
                       float* __restrict__ C, int M, int K, int Nc)
{
    const int BM = 64, BN = 64, BK = 16;
    __shared__ float As[BK][BM + 4];
    __shared__ float Ws[BK][BN];
    int t  = threadIdx.x;
    int tx = t & 15, ty = t >> 4;
    int m0 = blockIdx.y * BM, n0 = blockIdx.x * BN;
    float acc[4][4] = {};
    int la_m = t >> 2, la_k = (t & 3) * 4;
    int lw_k = t >> 4, lw_n = (t & 15) * 4;
    for (int k0 = 0; k0 < K; k0 += BK) {
        int arow = m0 + la_m;
        if (arow < M) {
            float4 v = *reinterpret_cast<const float4*>(A + (size_t)arow * K + k0 + la_k);
            As[la_k + 0][la_m] = v.x; As[la_k + 1][la_m] = v.y;
            As[la_k + 2][la_m] = v.z; As[la_k + 3][la_m] = v.w;
        } else {
            As[la_k + 0][la_m] = 0.f; As[la_k + 1][la_m] = 0.f;
            As[la_k + 2][la_m] = 0.f; As[la_k + 3][la_m] = 0.f;
        }
        {
            float4 v = *reinterpret_cast<const float4*>(W + (size_t)(k0 + lw_k) * Nc + n0 + lw_n);
            *reinterpret_cast<float4*>(&Ws[lw_k][lw_n]) = v;
        }
        __syncthreads();
        #pragma unroll
        for (int kk = 0; kk < BK; kk++) {
            float4 ra = *reinterpret_cast<const float4*>(&As[kk][ty * 4]);
            float4 rb = *reinterpret_cast<const float4*>(&Ws[kk][tx * 4]);
            float a[4] = {ra.x, ra.y, ra.z, ra.w};
            float b[4] = {rb.x, rb.y, rb.z, rb.w};
            #pragma unroll
            for (int i = 0; i < 4; i++)
                #pragma unroll
                for (int j = 0; j < 4; j++)
                    acc[i][j] += a[i] * b[j];
        }
        __syncthreads();
    }
    #pragma unroll
    for (int i = 0; i < 4; i++) {
        int row = m0 + ty * 4 + i;
        if (row >= M) continue;
        #pragma unroll
        for (int j = 0; j < 4; j++) {
            int col = n0 + tx * 4 + j;
            float v = acc[i][j];
            if (FLAGS & 1) v += bias[col];
            if (FLAGS & 2) v = gelu_f(v);
            if (FLAGS & 4) v += Res[(size_t)row * Nc + col];
            C[(size_t)row * Nc + col] = v;
        }
    }
}

// ---------------- graph prep ----------------
__global__ void deg_init_k() {
    int i = blockIdx.x * blockDim.x + threadIdx.x;
    if (i < NN) { g_deg[i] = 1.0f; g_icnt[i] = 0; }
    if (i < GG) g_cnt[i] = 0.0f;
}
__global__ void deg_edge_k(const int* __restrict__ dst) {
    int e = blockIdx.x * blockDim.x + threadIdx.x;
    if (e < NE) {
        int d = dst[e];
        atomicAdd(&g_deg[d], 1.0f);
        atomicAdd(&g_icnt[d], 1);
    }
}
__global__ void dinv_cnt_k(const int* __restrict__ batch) {
    int i = blockIdx.x * blockDim.x + threadIdx.x;
    if (i < NN) {
        g_dinv[i] = rsqrtf(g_deg[i]);
        atomicAdd(&g_cnt[batch[i]], 1.0f);
    }
}
// ---- CSR scan ----
__global__ void scan1_k() {
    __shared__ int sh[256];
    int i = blockIdx.x * 256 + threadIdx.x;
    int v = (i < NN) ? g_icnt[i] : 0;
    sh[threadIdx.x] = v;
    __syncthreads();
    for (int o = 1; o < 256; o <<= 1) {
        int tv = (threadIdx.x >= o) ? sh[threadIdx.x - o] : 0;
        __syncthreads();
        sh[threadIdx.x] += tv;
        __syncthreads();
    }
    if (i < NN) g_scan[i] = sh[threadIdx.x] - v;
    if (threadIdx.x == 255) g_bsum[blockIdx.x] = sh[255];
}
__global__ void scan2_k(int nb) {
    __shared__ int sh[512];
    int t = threadIdx.x;
    int v = (t < nb) ? g_bsum[t] : 0;
    sh[t] = v;
    __syncthreads();
    for (int o = 1; o < 512; o <<= 1) {
        int tv = (t >= o) ? sh[t - o] : 0;
        __syncthreads();
        sh[t] += tv;
        __syncthreads();
    }
    if (t < nb) g_bsum[t] = sh[t] - v;
}
__global__ void scan3_k() {
    int i = blockIdx.x * blockDim.x + threadIdx.x;
    if (i < NN) {
        int rp = g_scan[i] + g_bsum[i >> 8];
        g_rowptr[i] = rp;
        g_fill[i] = rp;
    }
    if (i == 0) g_rowptr[NN] = NE;
}
__global__ void scatter_k(const int* __restrict__ src, const int* __restrict__ dst) {
    int e = blockIdx.x * blockDim.x + threadIdx.x;
    if (e < NE) {
        int pos = atomicAdd(&g_fill[dst[e]], 1);
        g_ecol[pos] = src[e];
    }
}

// ---------------- per-hop elementwise (8 elems/thread, 16B accesses) ----------------
__global__ void vn_init_k(const float* __restrict__ vn_emb) {
    int i = blockIdx.x * blockDim.x + threadIdx.x;
    if (i < GG * HH) g_vn[i] = vn_emb[i & (HH - 1)];
}
__device__ __forceinline__ void unpack8(uint4 h, uint4 l, float* v) {
    __half2 h0 = *reinterpret_cast<__half2*>(&h.x), h1 = *reinterpret_cast<__half2*>(&h.y);
    __half2 h2 = *reinterpret_cast<__half2*>(&h.z), h3 = *reinterpret_cast<__half2*>(&h.w);
    __half2 l0 = *reinterpret_cast<__half2*>(&l.x), l1 = *reinterpret_cast<__half2*>(&l.y);
    __half2 l2 = *reinterpret_cast<__half2*>(&l.z), l3 = *reinterpret_cast<__half2*>(&l.w);
    v[0] = __low2float(h0) + __low2float(l0);  v[1] = __high2float(h0) + __high2float(l0);
    v[2] = __low2float(h1) + __low2float(l1);  v[3] = __high2float(h1) + __high2float(l1);
    v[4] = __low2float(h2) + __low2float(l2);  v[5] = __high2float(h2) + __high2float(l2);
    v[6] = __low2float(h3) + __low2float(l3);  v[7] = __high2float(h3) + __high2float(l3);
}
__device__ __forceinline__ void pack8(const float* v, uint4& h, uint4& l) {
    __half a0 = __float2half_rn(v[0]), a1 = __float2half_rn(v[1]);
    __half a2 = __float2half_rn(v[2]), a3 = __float2half_rn(v[3]);
    __half a4 = __float2half_rn(v[4]), a5 = __float2half_rn(v[5]);
    __half a6 = __float2half_rn(v[6]), a7 = __float2half_rn(v[7]);
    __half2 p;
    p = __halves2half2(a0, a1); h.x = *reinterpret_cast<uint32_t*>(&p);
    p = __halves2half2(a2, a3); h.y = *reinterpret_cast<uint32_t*>(&p);
    p = __halves2half2(a4, a5); h.z = *reinterpret_cast<uint32_t*>(&p);
    p = __halves2half2(a6, a7); h.w = *reinterpret_cast<uint32_t*>(&p);
    p = __floats2half2_rn(v[0] - __half2float(a0), v[1] - __half2float(a1));
    l.x = *reinterpret_cast<uint32_t*>(&p);
    p = __floats2half2_rn(v[2] - __half2float(a2), v[3] - __half2float(a3));
    l.y = *reinterpret_cast<uint32_t*>(&p);
    p = __floats2half2_rn(v[4] - __half2float(a4), v[5] - __half2float(a5));
    l.z = *reinterpret_cast<uint32_t*>(&p);
    p = __floats2half2_rn(v[6] - __half2float(a6), v[7] - __half2float(a7));
    l.w = *reinterpret_cast<uint32_t*>(&p);
}
// x += vn[batch]; 8 elems/thread; block 0 zeros BN accumulators + barrier counter
__global__ void addvn_split_k(const int* __restrict__ batch) {
    int i = blockIdx.x * blockDim.x + threadIdx.x;   // over EW/8
    if (blockIdx.x == 0) {
        if (threadIdx.x < HH) { g_sum[threadIdx.x] = 0.0; g_sumsq[threadIdx.x] = 0.0; }
        if (threadIdx.x == 0) g_barrier = 0;
    }
    if (i < NN * HH / 8) {
        int r  = i >> 4;
        int c8 = (i & 15) * 8;
        uint4* ph = reinterpret_cast<uint4*>(g_ahi) + i;
        uint4* pl = reinterpret_cast<uint4*>(g_alo) + i;
        uint4 hv = *ph, lv = *pl;
        float v[8];
        unpack8(hv, lv, v);
        const float* vnp = g_vn + batch[r] * HH + c8;
        float4 vn0 = *reinterpret_cast<const float4*>(vnp);
        float4 vn1 = *reinterpret_cast<const float4*>(vnp + 4);
        v[0] += vn0.x; v[1] += vn0.y; v[2] += vn0.z; v[3] += vn0.w;
        v[4] += vn1.x; v[5] += vn1.y; v[6] += vn1.z; v[7] += vn1.w;
        pack8(v, hv, lv);
        *ph = hv; *pl = lv;
    }
}
// CSR gather + conv bias + residual(split) + fp64 BN stats; last block finalizes BN
__global__ void gcn_gather_bn_k(const float* __restrict__ bias,
                                const float* __restrict__ gam, const float* __restrict__ bet) {
    __shared__ double s_sum[HH], s_sq[HH];
    __shared__ int s_last;
    int t = threadIdx.x;
    if (t < HH) { s_sum[t] = 0.0; s_sq[t] = 0.0; }
    __syncthreads();

    int gtid = blockIdx.x * blockDim.x + t;
    int warp = gtid >> 5, lane = gtid & 31;
    int nw = (gridDim.x * blockDim.x) >> 5;
    float4 b4 = *reinterpret_cast<const float4*>(bias + lane * 4);
    double s0 = 0, s1 = 0, s2 = 0, s3 = 0, q0 = 0, q1 = 0, q2 = 0, q3 = 0;
    for (int n = warp; n < NN; n += nw) {
        float di = g_dinv[n];
        size_t rb = (size_t)n * HH + lane * 4;
        float4 hv = *reinterpret_cast<const float4*>(g_h + rb);
        float sl = di * di;
        float ax = hv.x * sl, ay = hv.y * sl, az = hv.z * sl, aw = hv.w * sl;
        int e0 = g_rowptr[n], e1 = g_rowptr[n + 1];
        #pragma unroll 4
        for (int e = e0; e < e1; e++) {
            int sI = g_ecol[e];
            float nrm = g_dinv[sI] * di;
            float4 v = *reinterpret_cast<const float4*>(g_h + (size_t)sI * HH + lane * 4);
            ax += v.x * nrm; ay += v.y * nrm; az += v.z * nrm; aw += v.w * nrm;
        }
        __half2 xh0 = *reinterpret_cast<const __half2*>(g_ahi + rb);
        __half2 xh1 = *reinterpret_cast<const __half2*>(g_ahi + rb + 2);
        __half2 xl0 = *reinterpret_cast<const __half2*>(g_alo + rb);
        __half2 xl1 = *reinterpret_cast<const __half2*>(g_alo + rb + 2);
        float t0 = ax + b4.x + __low2float(xh0)  + __low2float(xl0);
        float t1 = ay + b4.y + __high2float(xh0) + __high2float(xl0);
        float t2 = az + b4.z + __low2float(xh1)  + __low2float(xl1);
        float t3 = aw + b4.w + __high2float(xh1) + __high2float(xl1);
        __half h0 = __float2half_rn(t0), h1 = __float2half_rn(t1);
        __half h2 = __float2half_rn(t2), h3 = __float2half_rn(t3);
        *reinterpret_cast<__half2*>(g_ahi + rb)     = __halves2half2(h0, h1);
        *reinterpret_cast<__half2*>(g_ahi + rb + 2) = __halves2half2(h2, h3);
        *reinterpret_cast<__half2*>(g_alo + rb) = __floats2half2_rn(
            t0 - __half2float(h0), t1 - __half2float(h1));
        *reinterpret_cast<__half2*>(g_alo + rb + 2) = __floats2half2_rn(
            t2 - __half2float(h2), t3 - __half2float(h3));
        s0 += t0; s1 += t1; s2 += t2; s3 += t3;
        q0 += (double)t0 * t0; q1 += (double)t1 * t1;
        q2 += (double)t2 * t2; q3 += (double)t3 * t3;
    }
    atomicAdd(&s_sum[lane * 4 + 0], s0); atomicAdd(&s_sq[lane * 4 + 0], q0);
    atomicAdd(&s_sum[lane * 4 + 1], s1); atomicAdd(&s_sq[lane * 4 + 1], q1);
    atomicAdd(&s_sum[lane * 4 + 2], s2); atomicAdd(&s_sq[lane * 4 + 2], q2);
    atomicAdd(&s_sum[lane * 4 + 3], s3); atomicAdd(&s_sq[lane * 4 + 3], q3);
    __syncthreads();
    if (t < HH) {
        atomicAdd(&g_sum[t],   s_sum[t]);
        atomicAdd(&g_sumsq[t], s_sq[t]);
    }
    // last-block BN finalize
    __threadfence();
    __syncthreads();
    if (t == 0) s_last = atomicAdd(&g_barrier, 1);
    __syncthreads();
    if (s_last == (int)gridDim.x - 1 && t < HH) {
        double mean = g_sum[t] / (double)NN;
        double var  = g_sumsq[t] / (double)NN - mean * mean;
        float a = gam[t] * rsqrtf((float)var + EPSV);
        g_bnA[t] = a;
        g_bnC[t] = bet[t] - (float)mean * a;
    }
}
// BN apply, 8 elems/thread; block 0 zeros g_pool
__global__ void bn_apply_split_k() {
    if (blockIdx.x == 0) {
        for (int p = threadIdx.x; p < GG * HH; p += 256) g_pool[p] = 0.0f;
    }
    int i = blockIdx.x * blockDim.x + threadIdx.x;   // over EW/8
    if (i < NN * HH / 8) {
        int c8 = (i & 15) * 8;
        uint4* ph = reinterpret_cast<uint4*>(g_ahi) + i;
        uint4* pl = reinterpret_cast<uint4*>(g_alo) + i;
        uint4 hv = *ph, lv = *pl;
        float v[8];
        unpack8(hv, lv, v);
        float4 A0 = *reinterpret_cast<const float4*>(g_bnA + c8);
        float4 A1 = *reinterpret_cast<const float4*>(g_bnA + c8 + 4);
        float4 C0 = *reinterpret_cast<const float4*>(g_bnC + c8);
        float4 C1 = *reinterpret_cast<const float4*>(g_bnC + c8 + 4);
        v[0] = v[0] * A0.x + C0.x; v[1] = v[1] * A0.y + C0.y;
        v[2] = v[2] * A0.z + C0.z; v[3] = v[3] * A0.w + C0.w;
        v[4] = v[4] * A1.x + C1.x; v[5] = v[5] * A1.y + C1.y;
        v[6] = v[6] * A1.z + C1.z; v[7] = v[7] * A1.w + C1.w;
        pack8(v, hv, lv);
        *ph = hv; *pl = lv;
    }
}

// ---------------- pooling (R15-proven: 64 half2-lanes x 4 row-subranges) ----------------
#define PROWS 128
__global__ void pool_k(const int* __restrict__ batch) {
    int lane = threadIdx.x & 63;
    int sub  = threadIdx.x >> 6;
    int r0 = blockIdx.x * PROWS + sub * (PROWS / 4);
    if (r0 >= NN) return;
    int r1 = min(r0 + PROWS / 4, NN);
    float a0 = 0.0f, a1 = 0.0f;
    int cur = batch[r0];
    for (int r = r0; r < r1; r++) {
        int g = batch[r];
        if (g != cur) {
            atomicAdd(&g_pool[cur * HH + lane * 2 + 0], a0);
            atomicAdd(&g_pool[cur * HH + lane * 2 + 1], a1);
            a0 = 0.0f; a1 = 0.0f; cur = g;
        }
        size_t idx = (size_t)r * HH + lane * 2;
        __half2 h2 = *reinterpret_cast<const __half2*>(g_ahi + idx);
        __half2 l2 = *reinterpret_cast<const __half2*>(g_alo + idx);
        a0 += __low2float(h2)  + __low2float(l2);
        a1 += __high2float(h2) + __high2float(l2);
    }
    atomicAdd(&g_pool[cur * HH + lane * 2 + 0], a0);
    atomicAdd(&g_pool[cur * HH + lane * 2 + 1], a1);
}
__global__ void vn_mlp1_k(const float* __restrict__ W1, const float* __restrict__ b1,
                          const float* __restrict__ g1, const float* __restrict__ be1) {
    int f = blockIdx.x;
    int g = threadIdx.x;
    float ic = 1.0f / fmaxf(g_cnt[g], 1.0f);
    float acc = b1[f];
    #pragma unroll 4
    for (int k = 0; k < HH; k++) {
        float vnk = g_vn[g * HH + k] + g_pool[g * HH + k] * ic;
        acc += vnk * W1[k * H2 + f];
    }
    __shared__ float sh[64], sh2[64];
    sh[g] = acc; sh2[g] = acc * acc;
    __syncthreads();
    for (int o = 32; o > 0; o >>= 1) {
        if (g < o) { sh[g] += sh[g + o]; sh2[g] += sh2[g + o]; }
        __syncthreads();
    }
    float mean = sh[0] * (1.0f / 64.0f);
    float var  = sh2[0] * (1.0f / 64.0f) - mean * mean;
    float a = g1[f] * rsqrtf(var + EPSV);
    float c = be1[f] - mean * a;
    g_vnh[g * H2 + f] = gelu_f(acc * a + c);
}
__global__ void vn_mlp2_k(const float* __restrict__ W2, const float* __restrict__ b2,
                          const float* __restrict__ g2, const float* __restrict__ be2) {
    int f = blockIdx.x;
    int g = threadIdx.x;
    float acc = b2[f];
    #pragma unroll 4
    for (int k = 0; k < H2; k++)
        acc += g_vnh[g * H2 + k] * W2[k * HH + f];
    __shared__ float sh[64], sh2[64];
    sh[g] = acc; sh2[g] = acc * acc;
    __syncthreads();
    for (int o = 32; o > 0; o >>= 1) {
        if (g < o) { sh[g] += sh[g + o]; sh2[g] += sh2[g + o]; }
        __syncthreads();
    }
    float mean = sh[0] * (1.0f / 64.0f);
    float var  = sh2[0] * (1.0f / 64.0f) - mean * mean;
    float a = g2[f] * rsqrtf(var + EPSV);
    float c = be2[f] - mean * a;
    g_vn[g * HH + f] = gelu_f(acc * a + c);
}

// ---------------- host ----------------
extern "C" void kernel_launch(void* const* d_in, const int* in_sizes, int n_in,
                              void* d_out, int out_size)
{
    const float* x_in   = (const float*)d_in[0];
    const int*   ei     = (const int*)  d_in[1];
    const int*   batch  = (const int*)  d_in[2];
    const float* pre_W1 = (const float*)d_in[3];
    const float* pre_b1 = (const float*)d_in[4];
    const float* pre_W2 = (const float*)d_in[5];
    const float* pre_b2 = (const float*)d_in[6];
    const float* conv_W = (const float*)d_in[7];
    const float* conv_b = (const float*)d_in[8];
    const float* bn_g   = (const float*)d_in[9];
    const float* bn_b   = (const float*)d_in[10];
    const float* ffn_W1 = (const float*)d_in[11];
    const float* ffn_b1 = (const float*)d_in[12];
    const float* ffn_W2 = (const float*)d_in[13];
    const float* ffn_b2 = (const float*)d_in[14];
    const float* vn_W1  = (const float*)d_in[15];
    const float* vn_b1  = (const float*)d_in[16];
    const float* vn_g1  = (const float*)d_in[17];
    const float* vn_be1 = (const float*)d_in[18];
    const float* vn_W2  = (const float*)d_in[19];
    const float* vn_b2  = (const float*)d_in[20];
    const float* vn_g2  = (const float*)d_in[21];
    const float* vn_be2 = (const float*)d_in[22];
    const float* vn_emb = (const float*)d_in[23];
    const float* post_W1= (const float*)d_in[24];
    const float* post_b1= (const float*)d_in[25];
    const float* post_W2= (const float*)d_in[26];
    const float* post_b2= (const float*)d_in[27];
    float* out = (float*)d_out;

    const int* src = ei;
    const int* dst = ei + NE;

    float *ph, *ppool, *pvnh;
    __half *pahi, *palo, *phhi, *phlo, *pwhi, *pwlo;
    cudaGetSymbolAddress((void**)&ph,   g_h);
    cudaGetSymbolAddress((void**)&ppool,g_pool);
    cudaGetSymbolAddress((void**)&pvnh, g_vnh);
    cudaGetSymbolAddress((void**)&pahi, g_ahi);
    cudaGetSymbolAddress((void**)&palo, g_alo);
    cudaGetSymbolAddress((void**)&phhi, g_hhi);
    cudaGetSymbolAddress((void**)&phlo, g_hlo);
    cudaGetSymbolAddress((void**)&pwhi, g_whi);
    cudaGetSymbolAddress((void**)&pwlo, g_wlo);

    cudaFuncSetAttribute(mma_gemm<11>, cudaFuncAttributeMaxDynamicSharedMemorySize, GSMEM);
    cudaFuncSetAttribute(mma_gemm<15>, cudaFuncAttributeMaxDynamicSharedMemorySize, GSMEM);
    cudaFuncSetAttribute(mma_gemm<16>, cudaFuncAttributeMaxDynamicSharedMemorySize, GSMEM);

    const int EW = NN * HH;
    dim3 blk(256);
    int gEW4 = (EW / 4 + 255) / 256;
    int gEW8 = (EW / 8 + 255) / 256;
    const int MT = (NN + 127) / 128;   // 782
    const int NB = (NN + 255) / 256;   // 391

    // launches 1-3, then #4 = mma_gemm<11> (pre1) — ncu -s 5 with 2 harness launches
    wprep_all_k<<<(WTOT + 255) / 256, blk>>>(pre_W1, pre_W2, conv_W, ffn_W1, ffn_W2); // 1
    split_k<<<gEW4, blk>>>(x_in, pahi, palo, EW / 4);                                 // 2
    deg_init_k<<<NB, blk>>>();                                                        // 3
    mma_gemm<11><<<dim3(4, MT), 256, GSMEM>>>(pahi, palo, pwhi + OW_PRE1, pwlo + OW_PRE1,
        pre_b1, nullptr, nullptr, nullptr, phhi, phlo, NN, HH, H2);                   // 4 <- ncu
    deg_edge_k<<<(NE + 255) / 256, blk>>>(dst);
    dinv_cnt_k<<<NB, blk>>>(batch);
    scan1_k<<<NB, blk>>>();
    scan2_k<<<1, 512>>>(NB);
    scan3_k<<<NB, blk>>>();
    scatter_k<<<(NE + 255) / 256, blk>>>(src, dst);
    // pre2: x = gelu(hid@pre_W2+b) -> splits (ahi/alo)
    mma_gemm<11><<<dim3(2, MT), 256, GSMEM>>>(phhi, phlo, pwhi + OW_PRE2, pwlo + OW_PRE2,
        pre_b2, nullptr, nullptr, nullptr, pahi, palo, NN, H2, HH);
    vn_init_k<<<(GG * HH + 255) / 256, blk>>>(vn_emb);

    for (int i = 0; i < NHOPS; i++) {
        addvn_split_k<<<gEW8, blk>>>(batch);
        // h = x @ conv_W[i]  (fp32 out, gather-friendly)
        mma_gemm<16><<<dim3(2, MT), 256, GSMEM>>>(pahi, palo, pwhi + OW_CONV(i), pwlo + OW_CONV(i),
            nullptr, nullptr, nullptr, ph, nullptr, nullptr, NN, HH, HH);
        gcn_gather_bn_k<<<512, 256>>>(conv_b + (size_t)i * HH,
                                      bn_g + (size_t)i * HH, bn_b + (size_t)i * HH);
        bn_apply_split_k<<<gEW8, blk>>>();
        // hid = gelu(x@ffn_W1+b) -> splits
        mma_gemm<11><<<dim3(4, MT), 256, GSMEM>>>(pahi, palo, pwhi + OW_FFN1(i), pwlo + OW_FFN1(i),
            ffn_b1 + (size_t)i * H2, nullptr, nullptr, nullptr, phhi, phlo, NN, HH, H2);
        // x = gelu(hid@ffn_W2+b) + x  -> splits (in-place residual)
        mma_gemm<15><<<dim3(2, MT), 256, GSMEM>>>(phhi, phlo, pwhi + OW_FFN2(i), pwlo + OW_FFN2(i),
            ffn_b2 + (size_t)i * HH, pahi, palo, nullptr, pahi, palo, NN, H2, HH);
        if (i < NHOPS - 1) {
            pool_k<<<(NN + PROWS - 1) / PROWS, blk>>>(batch);
            vn_mlp1_k<<<H2, GG>>>(vn_W1 + (size_t)i * HH * H2, vn_b1 + (size_t)i * H2,
                                  vn_g1 + (size_t)i * H2, vn_be1 + (size_t)i * H2);
            vn_mlp2_k<<<HH, GG>>>(vn_W2 + (size_t)i * H2 * HH, vn_b2 + (size_t)i * HH,
                                  vn_g2 + (size_t)i * HH, vn_be2 + (size_t)i * HH);
        }
    }

    // ---- final pool + post-FFNN (fp32) ----
    pool_k<<<(NN + PROWS - 1) / PROWS, blk>>>(batch);
    dim3 gp1(H2 / 64, 1);
    gemm64<3><<<gp1, blk>>>(ppool, post_W1, post_b1, nullptr, pvnh, GG, HH, H2);
    dim3 gp2(HH / 64, 1);
    gemm64<3><<<gp2, blk>>>(pvnh, post_W2, post_b2, nullptr, out, GG, H2, HH);
}